// round 5
// baseline (speedup 1.0000x reference)
#include <cuda_runtime.h>
#include <math.h>

// Problem constants (fixed shapes from reference)
#define BATCH 4
#define TLEN  8192
#define EMB   1024
#define DH    64
#define MF    8          // m features -> 2m = 16 total (cos|sin)
#define NJ    80         // fused output cols: 8 p_q + 8 p_k + 64 v
#define TM    128        // tokens per phase-1 tile
#define KC    32         // K-chunk
#define NTILE ((BATCH*TLEN)/TM)   // 256
#define NFEAT (2*MF)     // 16
#define INV_SQRT_M 0.35355339059327376f   // 1/sqrt(8)

// ---- device scratch (no allocations allowed) ----
__device__ float g_W[EMB*NJ];                 // folded weights [1024][80]
__device__ float g_bias[NJ];                  // folded biases
__device__ float g_pq[BATCH*TLEN*MF];         // raw p_q per token (1 MB)
__device__ float g_Spart[NTILE*NFEAT*DH];     // per-tile partial S (1 MB)
__device__ float g_S[BATCH*NFEAT*DH];         // reduced S [4][16][64]

// ============================================================
// prep: fold Wq@w, Wk@w into g_W cols 0..15; copy Wv into 16..79.
// ============================================================
__global__ void prep_kernel(const float* __restrict__ w,
                            const float* __restrict__ Wq, const float* __restrict__ bq,
                            const float* __restrict__ Wk, const float* __restrict__ bk,
                            const float* __restrict__ Wv, const float* __restrict__ bv) {
    int g = blockIdx.x * blockDim.x + threadIdx.x;
    if (g < NJ) {
        float bb;
        if (g < MF) {
            bb = 0.f;
            for (int d = 0; d < DH; d++) bb += bq[d] * w[d*MF + g];
        } else if (g < 2*MF) {
            int jj = g - MF;
            bb = 0.f;
            for (int d = 0; d < DH; d++) bb += bk[d] * w[d*MF + jj];
        } else {
            bb = bv[g - 2*MF];
        }
        g_bias[g] = bb;
    }
    if (g >= EMB*NJ) return;
    int e = g / NJ;
    int j = g - e*NJ;
    float val;
    if (j < MF) {
        val = 0.f;
        for (int d = 0; d < DH; d++) val += Wq[e*DH + d] * w[d*MF + j];
    } else if (j < 2*MF) {
        int jj = j - MF;
        val = 0.f;
        for (int d = 0; d < DH; d++) val += Wk[e*DH + d] * w[d*MF + jj];
    } else {
        val = Wv[e*DH + (j - 2*MF)];
    }
    g_W[g] = val;
}

// ============================================================
// phase 1: fused GEMM tile [128 tok x 80] + p_q flush + Kp map +
//          per-tile partial S (deterministic: own slab, no atomics)
// ============================================================
union SmemP1 {
    struct { float xs[KC][TM + 1]; float ws[KC][NJ]; } a;  // 16512 + 10240 B
    float res[TM][NJ + 1];                                  // 41472 B
};

__global__ __launch_bounds__(256) void phase1_kernel(const float* __restrict__ x) {
    __shared__ SmemP1 sm;
    const int tid  = threadIdx.x;
    const int tile = blockIdx.x;
    const int t0   = tile * TM;                 // global token base (batch folded)
    const float* xrow = x + (size_t)t0 * EMB;
    const int tcol = tid & 31;                  // token lane
    const int trow = tid >> 5;                  // output-col group (0..7)

    float acc[4][10];
    #pragma unroll
    for (int i = 0; i < 4; i++)
        #pragma unroll
        for (int jj = 0; jj < 10; jj++) acc[i][jj] = 0.f;

    for (int ko = 0; ko < EMB; ko += KC) {
        // load x tile [128 tok x 32 k], transpose to xs[k][tok] (stride 129 -> 2-way max)
        #pragma unroll
        for (int i = 0; i < 4; i++) {
            int idx = tid + i * 256;            // 0..1023 float4s
            int tok = idx >> 3;                 // 8 float4 per token row
            int k4  = (idx & 7) << 2;
            float4 v4 = *reinterpret_cast<const float4*>(xrow + (size_t)tok * EMB + ko + k4);
            sm.a.xs[k4 + 0][tok] = v4.x;
            sm.a.xs[k4 + 1][tok] = v4.y;
            sm.a.xs[k4 + 2][tok] = v4.z;
            sm.a.xs[k4 + 3][tok] = v4.w;
        }
        // load W tile [32 k x 80 j]
        #pragma unroll
        for (int i = 0; i < 10; i++) {
            int idx = tid + i * 256;            // 0..2559
            int k = idx / NJ;
            int j = idx - k * NJ;
            sm.a.ws[k][j] = g_W[(ko + k) * NJ + j];
        }
        __syncthreads();

        #pragma unroll 8
        for (int k = 0; k < KC; k++) {
            float wr[10];
            #pragma unroll
            for (int jj = 0; jj < 10; jj++) wr[jj] = sm.a.ws[k][trow * 10 + jj];  // warp-broadcast
            #pragma unroll
            for (int i = 0; i < 4; i++) {
                float xv = sm.a.xs[k][tcol + 32 * i];                              // conflict-free
                #pragma unroll
                for (int jj = 0; jj < 10; jj++)
                    acc[i][jj] = fmaf(xv, wr[jj], acc[i][jj]);
            }
        }
        __syncthreads();
    }

    // bias + stage results to res[tok][j] (union reuse; reads all done)
    #pragma unroll
    for (int i = 0; i < 4; i++) {
        int tok = tcol + 32 * i;
        #pragma unroll
        for (int jj = 0; jj < 10; jj++) {
            int j = trow * 10 + jj;
            sm.res[tok][j] = acc[i][jj] + g_bias[j];
        }
    }
    __syncthreads();

    // flush raw p_q (cols 0..7) -> contiguous, coalesced
    #pragma unroll
    for (int i = 0; i < 4; i++) {
        int idx = tid + i * 256;                // 0..1023 = tok*8 + m
        int tok = idx >> 3;
        int mq  = idx & 7;
        g_pq[(size_t)t0 * MF + idx] = sm.res[tok][mq];
    }
    __syncthreads();

    // Kp = [cos(p_k), sin(p_k)]/sqrt(m), in place: cos -> slots 0..7, sin -> 8..15
    #pragma unroll
    for (int i = 0; i < 4; i++) {
        int idx = tid + i * 256;
        int tok = idx >> 3;
        int mm  = idx & 7;
        float p = sm.res[tok][MF + mm];
        float sv, cv;
        sincosf(p, &sv, &cv);
        sm.res[tok][mm]      = cv * INV_SQRT_M;
        sm.res[tok][MF + mm] = sv * INV_SQRT_M;
    }
    __syncthreads();

    // partial S[16][64] for this tile; thread = (fgroup of 4 feats, d)
    const int d  = tid & 63;
    const int fg = tid >> 6;                    // 0..3
    float sacc[4] = {0.f, 0.f, 0.f, 0.f};
    for (int tok = 0; tok < TM; tok++) {
        float v = sm.res[tok][2*MF + d];        // conflict-free (consecutive d)
        #pragma unroll
        for (int ff = 0; ff < 4; ff++)
            sacc[ff] = fmaf(sm.res[tok][fg * 4 + ff], v, sacc[ff]);  // warp-broadcast
    }
    float* Sp = g_Spart + (size_t)tile * (NFEAT * DH);
    #pragma unroll
    for (int ff = 0; ff < 4; ff++)
        Sp[(fg * 4 + ff) * DH + d] = sacc[ff];
}

// ============================================================
// reduce: S[b][f][d] = sum over 64 tiles of that batch (deterministic order)
// ============================================================
__global__ void reduce_kernel() {
    int g  = blockIdx.x * blockDim.x + threadIdx.x;   // 0..4095
    int b  = g >> 10;
    int fd = g & 1023;
    const float* base = g_Spart + (size_t)b * 64 * (NFEAT * DH) + fd;
    float s = 0.f;
    #pragma unroll
    for (int tt = 0; tt < 64; tt++) s += base[(size_t)tt * (NFEAT * DH)];
    g_S[g] = s;
}

// ============================================================
// phase 2: y[t][d] = sum_f qP[t][f] * S[b][f][d]; 1 thread per token
// ============================================================
__global__ __launch_bounds__(256) void phase2_kernel(float* __restrict__ y) {
    __shared__ float Ss[NFEAT * DH];            // 4 KB
    const int tid = threadIdx.x;
    const int t0  = blockIdx.x * 256;           // 256 tokens per block
    const int b   = t0 / TLEN;

    #pragma unroll
    for (int i = 0; i < 4; i++) Ss[tid + i * 256] = g_S[b * (NFEAT * DH) + tid + i * 256];
    __syncthreads();

    const float* pq = g_pq + (size_t)(t0 + tid) * MF;
    float4 pa = *reinterpret_cast<const float4*>(pq);
    float4 pb = *reinterpret_cast<const float4*>(pq + 4);
    float pv[8] = {pa.x, pa.y, pa.z, pa.w, pb.x, pb.y, pb.z, pb.w};
    float q[NFEAT];
    #pragma unroll
    for (int m2 = 0; m2 < 8; m2++) {
        float sv, cv;
        sincosf(pv[m2], &sv, &cv);
        q[m2]     = cv * INV_SQRT_M;
        q[8 + m2] = sv * INV_SQRT_M;
    }

    float out[DH];
    #pragma unroll
    for (int d = 0; d < DH; d++) out[d] = 0.f;

    #pragma unroll
    for (int f = 0; f < NFEAT; f++) {
        float qf = q[f];
        const float4* row = reinterpret_cast<const float4*>(Ss + f * DH);  // full-warp broadcast
        #pragma unroll
        for (int j = 0; j < 16; j++) {
            float4 sv = row[j];
            out[4*j + 0] = fmaf(qf, sv.x, out[4*j + 0]);
            out[4*j + 1] = fmaf(qf, sv.y, out[4*j + 1]);
            out[4*j + 2] = fmaf(qf, sv.z, out[4*j + 2]);
            out[4*j + 3] = fmaf(qf, sv.w, out[4*j + 3]);
        }
    }

    float4* yo = reinterpret_cast<float4*>(y + (size_t)(t0 + tid) * DH);
    #pragma unroll
    for (int j = 0; j < 16; j++)
        yo[j] = make_float4(out[4*j], out[4*j + 1], out[4*j + 2], out[4*j + 3]);
}

// ============================================================
extern "C" void kernel_launch(void* const* d_in, const int* in_sizes, int n_in,
                              void* d_out, int out_size) {
    (void)in_sizes; (void)n_in; (void)out_size;
    const float* x  = (const float*)d_in[0];
    const float* w  = (const float*)d_in[1];
    const float* Wq = (const float*)d_in[2];
    const float* bq = (const float*)d_in[3];
    const float* Wk = (const float*)d_in[4];
    const float* bk = (const float*)d_in[5];
    const float* Wv = (const float*)d_in[6];
    const float* bv = (const float*)d_in[7];
    float* y = (float*)d_out;

    prep_kernel<<<(EMB * NJ + 255) / 256, 256>>>(w, Wq, bq, Wk, bk, Wv, bv);
    phase1_kernel<<<NTILE, 256>>>(x);
    reduce_kernel<<<(BATCH * NFEAT * DH) / 256, 256>>>();
    phase2_kernel<<<(BATCH * TLEN) / 256, 256>>>(y);
}

// round 6
// speedup vs baseline: 1.2110x; 1.2110x over previous
#include <cuda_runtime.h>
#include <math.h>

// Problem constants (fixed shapes from reference)
#define BATCH 4
#define TLEN  8192
#define EMB   1024
#define DH    64
#define MF    8          // m features -> 2m = 16 total (cos|sin)
#define NJ    80         // fused output cols: 8 p_q + 8 p_k + 64 v
#define TM    128        // tokens per phase-1 tile
#define KC    32         // K-chunk
#define NTILE ((BATCH*TLEN)/TM)   // 256
#define NFEAT (2*MF)     // 16
#define INV_SQRT_M 0.35355339059327376f   // 1/sqrt(8)

// ---- device scratch (no allocations allowed) ----
__device__ float g_W[EMB*NJ];                 // folded weights [1024][80]
__device__ float g_bias[NJ];                  // folded biases
__device__ float g_pq[BATCH*TLEN*MF];         // raw p_q per token (1 MB)
__device__ float g_Spart[NTILE*NFEAT*DH];     // per-tile partial S (1 MB)
__device__ float g_S[BATCH*NFEAT*DH];         // reduced S [4][16][64]

// ---- packed f32x2 helpers (FFMA2: 2 MACs per instruction, ptxas never emits this) ----
__device__ __forceinline__ unsigned long long ffma2(unsigned long long a,
                                                    unsigned long long b,
                                                    unsigned long long c) {
    unsigned long long d;
    asm("fma.rn.f32x2 %0, %1, %2, %3;" : "=l"(d) : "l"(a), "l"(b), "l"(c));
    return d;
}
__device__ __forceinline__ unsigned long long dup2(float v) {
    unsigned long long d;
    unsigned int r = __float_as_uint(v);
    asm("mov.b64 %0, {%1, %1};" : "=l"(d) : "r"(r));
    return d;
}

// ============================================================
// prep: fold Wq@w, Wk@w into g_W cols 0..15; copy Wv into 16..79.
// ============================================================
__global__ void prep_kernel(const float* __restrict__ w,
                            const float* __restrict__ Wq, const float* __restrict__ bq,
                            const float* __restrict__ Wk, const float* __restrict__ bk,
                            const float* __restrict__ Wv, const float* __restrict__ bv) {
    int g = blockIdx.x * blockDim.x + threadIdx.x;
    if (g < NJ) {
        float bb;
        if (g < MF) {
            bb = 0.f;
            for (int d = 0; d < DH; d++) bb += bq[d] * w[d*MF + g];
        } else if (g < 2*MF) {
            int jj = g - MF;
            bb = 0.f;
            for (int d = 0; d < DH; d++) bb += bk[d] * w[d*MF + jj];
        } else {
            bb = bv[g - 2*MF];
        }
        g_bias[g] = bb;
    }
    if (g >= EMB*NJ) return;
    int e = g / NJ;
    int j = g - e*NJ;
    float val;
    if (j < MF) {
        val = 0.f;
        for (int d = 0; d < DH; d++) val += Wq[e*DH + d] * w[d*MF + j];
    } else if (j < 2*MF) {
        int jj = j - MF;
        val = 0.f;
        for (int d = 0; d < DH; d++) val += Wk[e*DH + d] * w[d*MF + jj];
    } else {
        val = Wv[e*DH + (j - 2*MF)];
    }
    g_W[g] = val;
}

// ============================================================
// phase 1: fused GEMM tile [128 tok x 80] via packed FFMA2 + p_q flush +
//          Kp map + per-tile partial S (deterministic: own slab, no atomics)
// ============================================================
union SmemP1 {
    struct { float xs[KC][TM + 1]; float ws[KC][NJ]; } a;  // 16512 + 10240 B
    float res[TM][NJ + 1];                                  // 41472 B
};

__global__ __launch_bounds__(256) void phase1_kernel(const float* __restrict__ x) {
    __shared__ SmemP1 sm;
    const int tid  = threadIdx.x;
    const int tile = blockIdx.x;
    const int t0   = tile * TM;                 // global token base (batch folded)
    const float* xrow = x + (size_t)t0 * EMB;
    const int tcol = tid & 31;                  // token lane
    const int trow = tid >> 5;                  // output-col group (0..7)

    // 4 token-slots x 5 packed j-pairs (covers 10 j columns)
    unsigned long long acc[4][5];
    #pragma unroll
    for (int i = 0; i < 4; i++)
        #pragma unroll
        for (int jj = 0; jj < 5; jj++) acc[i][jj] = 0ull;

    for (int ko = 0; ko < EMB; ko += KC) {
        // load x tile [128 tok x 32 k], transpose to xs[k][tok] (stride 129 -> 2-way max)
        #pragma unroll
        for (int i = 0; i < 4; i++) {
            int idx = tid + i * 256;            // 0..1023 float4s
            int tok = idx >> 3;                 // 8 float4 per token row
            int k4  = (idx & 7) << 2;
            float4 v4 = *reinterpret_cast<const float4*>(xrow + (size_t)tok * EMB + ko + k4);
            sm.a.xs[k4 + 0][tok] = v4.x;
            sm.a.xs[k4 + 1][tok] = v4.y;
            sm.a.xs[k4 + 2][tok] = v4.z;
            sm.a.xs[k4 + 3][tok] = v4.w;
        }
        // load W tile [32 k x 80 j]
        #pragma unroll
        for (int i = 0; i < 10; i++) {
            int idx = tid + i * 256;            // 0..2559
            int k = idx / NJ;
            int j = idx - k * NJ;
            sm.a.ws[k][j] = g_W[(ko + k) * NJ + j];
        }
        __syncthreads();

        #pragma unroll 8
        for (int k = 0; k < KC; k++) {
            // 5 x LDS.64: natural float2 pairs of W columns (warp-broadcast, 8B-aligned)
            unsigned long long w2[5];
            #pragma unroll
            for (int jj = 0; jj < 5; jj++)
                w2[jj] = *reinterpret_cast<const unsigned long long*>(
                             &sm.a.ws[k][trow * 10 + 2 * jj]);
            #pragma unroll
            for (int i = 0; i < 4; i++) {
                unsigned long long x2 = dup2(sm.a.xs[k][tcol + 32 * i]);  // conflict-free LDS.32
                #pragma unroll
                for (int jj = 0; jj < 5; jj++)
                    acc[i][jj] = ffma2(x2, w2[jj], acc[i][jj]);
            }
        }
        __syncthreads();
    }

    // bias + stage results to res[tok][j] (union reuse; reads all done)
    #pragma unroll
    for (int i = 0; i < 4; i++) {
        int tok = tcol + 32 * i;
        #pragma unroll
        for (int jj = 0; jj < 5; jj++) {
            int j = trow * 10 + 2 * jj;
            union { unsigned long long u; float2 f; } cvt;
            cvt.u = acc[i][jj];
            sm.res[tok][j]     = cvt.f.x + g_bias[j];
            sm.res[tok][j + 1] = cvt.f.y + g_bias[j + 1];
        }
    }
    __syncthreads();

    // flush raw p_q (cols 0..7) -> contiguous, coalesced
    #pragma unroll
    for (int i = 0; i < 4; i++) {
        int idx = tid + i * 256;                // 0..1023 = tok*8 + m
        int tok = idx >> 3;
        int mq  = idx & 7;
        g_pq[(size_t)t0 * MF + idx] = sm.res[tok][mq];
    }
    __syncthreads();

    // Kp = [cos(p_k), sin(p_k)]/sqrt(m), in place: cos -> slots 0..7, sin -> 8..15
    #pragma unroll
    for (int i = 0; i < 4; i++) {
        int idx = tid + i * 256;
        int tok = idx >> 3;
        int mm  = idx & 7;
        float p = sm.res[tok][MF + mm];
        float sv, cv;
        sincosf(p, &sv, &cv);
        sm.res[tok][mm]      = cv * INV_SQRT_M;
        sm.res[tok][MF + mm] = sv * INV_SQRT_M;
    }
    __syncthreads();

    // partial S[16][64] for this tile; thread = (fgroup of 4 feats, d)
    const int d  = tid & 63;
    const int fg = tid >> 6;                    // 0..3
    float sacc[4] = {0.f, 0.f, 0.f, 0.f};
    for (int tok = 0; tok < TM; tok++) {
        float v = sm.res[tok][2*MF + d];        // conflict-free (consecutive d)
        #pragma unroll
        for (int ff = 0; ff < 4; ff++)
            sacc[ff] = fmaf(sm.res[tok][fg * 4 + ff], v, sacc[ff]);  // warp-broadcast
    }
    float* Sp = g_Spart + (size_t)tile * (NFEAT * DH);
    #pragma unroll
    for (int ff = 0; ff < 4; ff++)
        Sp[(fg * 4 + ff) * DH + d] = sacc[ff];
}

// ============================================================
// reduce: S[b][f][d] = sum over 64 tiles of that batch (deterministic order)
// ============================================================
__global__ void reduce_kernel() {
    int g  = blockIdx.x * blockDim.x + threadIdx.x;   // 0..4095
    int b  = g >> 10;
    int fd = g & 1023;
    const float* base = g_Spart + (size_t)b * 64 * (NFEAT * DH) + fd;
    float s = 0.f;
    #pragma unroll
    for (int tt = 0; tt < 64; tt++) s += base[(size_t)tt * (NFEAT * DH)];
    g_S[g] = s;
}

// ============================================================
// phase 2: y[t][d] = sum_f qP[t][f] * S[b][f][d]; 1 thread per token.
// 128-thread blocks -> grid 256 (>148 SMs) for occupancy/latency hiding.
// ============================================================
__global__ __launch_bounds__(128) void phase2_kernel(float* __restrict__ y) {
    __shared__ float Ss[NFEAT * DH];            // 4 KB
    const int tid = threadIdx.x;
    const int t0  = blockIdx.x * 128;           // 128 tokens per block
    const int b   = t0 / TLEN;

    #pragma unroll
    for (int i = 0; i < 8; i++) Ss[tid + i * 128] = g_S[b * (NFEAT * DH) + tid + i * 128];
    __syncthreads();

    const float* pq = g_pq + (size_t)(t0 + tid) * MF;
    float4 pa = *reinterpret_cast<const float4*>(pq);
    float4 pb = *reinterpret_cast<const float4*>(pq + 4);
    float pv[8] = {pa.x, pa.y, pa.z, pa.w, pb.x, pb.y, pb.z, pb.w};
    float q[NFEAT];
    #pragma unroll
    for (int m2 = 0; m2 < 8; m2++) {
        float sv, cv;
        sincosf(pv[m2], &sv, &cv);
        q[m2]     = cv * INV_SQRT_M;
        q[8 + m2] = sv * INV_SQRT_M;
    }

    float out[DH];
    #pragma unroll
    for (int d = 0; d < DH; d++) out[d] = 0.f;

    #pragma unroll
    for (int f = 0; f < NFEAT; f++) {
        float qf = q[f];
        const float4* row = reinterpret_cast<const float4*>(Ss + f * DH);  // full-warp broadcast
        #pragma unroll
        for (int j = 0; j < 16; j++) {
            float4 sv = row[j];
            out[4*j + 0] = fmaf(qf, sv.x, out[4*j + 0]);
            out[4*j + 1] = fmaf(qf, sv.y, out[4*j + 1]);
            out[4*j + 2] = fmaf(qf, sv.z, out[4*j + 2]);
            out[4*j + 3] = fmaf(qf, sv.w, out[4*j + 3]);
        }
    }

    float4* yo = reinterpret_cast<float4*>(y + (size_t)(t0 + tid) * DH);
    #pragma unroll
    for (int j = 0; j < 16; j++)
        yo[j] = make_float4(out[4*j], out[4*j + 1], out[4*j + 2], out[4*j + 3]);
}

// ============================================================
extern "C" void kernel_launch(void* const* d_in, const int* in_sizes, int n_in,
                              void* d_out, int out_size) {
    (void)in_sizes; (void)n_in; (void)out_size;
    const float* x  = (const float*)d_in[0];
    const float* w  = (const float*)d_in[1];
    const float* Wq = (const float*)d_in[2];
    const float* bq = (const float*)d_in[3];
    const float* Wk = (const float*)d_in[4];
    const float* bk = (const float*)d_in[5];
    const float* Wv = (const float*)d_in[6];
    const float* bv = (const float*)d_in[7];
    float* y = (float*)d_out;

    prep_kernel<<<(EMB * NJ + 255) / 256, 256>>>(w, Wq, bq, Wk, bk, Wv, bv);
    phase1_kernel<<<NTILE, 256>>>(x);
    reduce_kernel<<<(BATCH * NFEAT * DH) / 256, 256>>>();
    phase2_kernel<<<(BATCH * TLEN) / 128, 128>>>(y);
}

// round 8
// speedup vs baseline: 2.2930x; 1.8935x over previous
#include <cuda_runtime.h>
#include <cuda_bf16.h>
#include <math.h>
#include <stdint.h>

// Problem constants
#define BATCH 4
#define TLEN  8192
#define EMB   1024
#define DH    64
#define MF    8
#define NJ    80          // 8 p_q + 8 p_k + 64 v
#define TM    128         // tokens per phase-1 tile (MMA M)
#define KC    32          // K per staged chunk (bf16)
#define NCHUNK (EMB/KC)   // 32
#define NTILE ((BATCH*TLEN)/TM)   // 256
#define NFEAT (2*MF)
#define INV_SQRT_M 0.35355339059327376f

// ---- device scratch (no allocations allowed) ----
__device__ __nv_bfloat16 g_WBh[EMB*NJ];   // folded W [e][j] bf16 hi
__device__ __nv_bfloat16 g_WBl[EMB*NJ];   // bf16 lo residual
__device__ float g_bias[NJ];
__device__ float g_pq[BATCH*TLEN*MF];
__device__ float g_Spart[NTILE*NFEAT*DH];
__device__ float g_S[BATCH*NFEAT*DH];

// ---- helpers ----
__device__ __forceinline__ uint32_t smem_u32(const void* p) {
    uint32_t a;
    asm("{ .reg .u64 t; cvta.to.shared.u64 t, %1; cvt.u32.u64 %0, t; }" : "=r"(a) : "l"(p));
    return a;
}
__device__ __forceinline__ void ldsm_x4(uint32_t* r, uint32_t addr) {
    asm volatile("ldmatrix.sync.aligned.m8n8.x4.shared.b16 {%0,%1,%2,%3}, [%4];"
        : "=r"(r[0]), "=r"(r[1]), "=r"(r[2]), "=r"(r[3]) : "r"(addr));
}
__device__ __forceinline__ void ldsm_x4_t(uint32_t* r, uint32_t addr) {
    asm volatile("ldmatrix.sync.aligned.m8n8.x4.trans.shared.b16 {%0,%1,%2,%3}, [%4];"
        : "=r"(r[0]), "=r"(r[1]), "=r"(r[2]), "=r"(r[3]) : "r"(addr));
}
__device__ __forceinline__ void mma_bf16(float* c, const uint32_t* a, const uint32_t* b) {
    asm volatile("mma.sync.aligned.m16n8k16.row.col.f32.bf16.bf16.f32 "
        "{%0,%1,%2,%3}, {%4,%5,%6,%7}, {%8,%9}, {%0,%1,%2,%3};"
        : "+f"(c[0]), "+f"(c[1]), "+f"(c[2]), "+f"(c[3])
        : "r"(a[0]), "r"(a[1]), "r"(a[2]), "r"(a[3]), "r"(b[0]), "r"(b[1]));
}
// split fp32 pair -> packed bf16 hi + bf16 lo(residual)
__device__ __forceinline__ void split_pack(float vx, float vy, uint32_t& hi, uint32_t& lo) {
    __nv_bfloat162 h = __float22bfloat162_rn(make_float2(vx, vy));
    float2 hf = __bfloat1622float2(h);
    __nv_bfloat162 l = __float22bfloat162_rn(make_float2(vx - hf.x, vy - hf.y));
    hi = *reinterpret_cast<uint32_t*>(&h);
    lo = *reinterpret_cast<uint32_t*>(&l);
}

// ============================================================
// prep: fold Wq@w, Wk@w + Wv into bf16 hi/lo [e][j]; biases.
// ============================================================
__global__ void prep_kernel(const float* __restrict__ w,
                            const float* __restrict__ Wq, const float* __restrict__ bq,
                            const float* __restrict__ Wk, const float* __restrict__ bk,
                            const float* __restrict__ Wv, const float* __restrict__ bv) {
    int g = blockIdx.x * blockDim.x + threadIdx.x;
    if (g < NJ) {
        float bb;
        if (g < MF) {
            bb = 0.f;
            for (int d = 0; d < DH; d++) bb += bq[d] * w[d*MF + g];
        } else if (g < 2*MF) {
            int jj = g - MF;
            bb = 0.f;
            for (int d = 0; d < DH; d++) bb += bk[d] * w[d*MF + jj];
        } else {
            bb = bv[g - 2*MF];
        }
        g_bias[g] = bb;
    }
    if (g >= EMB*NJ) return;
    int e = g / NJ;
    int j = g - e*NJ;
    float val;
    if (j < MF) {
        val = 0.f;
        for (int d = 0; d < DH; d++) val += Wq[e*DH + d] * w[d*MF + j];
    } else if (j < 2*MF) {
        int jj = j - MF;
        val = 0.f;
        for (int d = 0; d < DH; d++) val += Wk[e*DH + d] * w[d*MF + jj];
    } else {
        val = Wv[e*DH + (j - 2*MF)];
    }
    __nv_bfloat16 h = __float2bfloat16(val);
    float lo = val - __bfloat162float(h);
    g_WBh[g] = h;
    g_WBl[g] = __float2bfloat16(lo);
}

// ============================================================
// phase 1: HMMA (mma.sync bf16, 3-term error split) GEMM [128 x 80]
//          + p_q flush + sincos Kp + deterministic per-tile S partial
// ============================================================
// smem: A pad to 40 bf16/row (80B), B pad to 88 bf16/row (176B)
union SmemP1 {
    struct {
        __nv_bfloat16 a_hi[TM][40];   // 10240 B
        __nv_bfloat16 a_lo[TM][40];   // 10240 B
        __nv_bfloat16 b_hi[KC][88];   //  5632 B
        __nv_bfloat16 b_lo[KC][88];   //  5632 B
    } a;                               // 31744 B
    float res[TM][82];                 // 41984 B
};
#define OFF_ALO 10240
#define OFF_BHI 20480
#define OFF_BLO 26112

__global__ __launch_bounds__(256) void phase1_kernel(const float* __restrict__ x) {
    __shared__ SmemP1 sm;
    const int tid  = threadIdx.x;
    const int lane = tid & 31;
    const int w    = tid >> 5;                 // warp id 0..7 -> M rows 16w..16w+15
    const int tile = blockIdx.x;
    const float* xrow = x + (size_t)tile * TM * EMB;
    char* smc = reinterpret_cast<char*>(&sm);
    const uint32_t sbase = smem_u32(&sm);

    // per-lane ldmatrix base addresses
    const uint32_t aHiAddr = sbase + (uint32_t)((16*w + (lane & 15)) * 80 + ((lane >> 4) * 8) * 2);
    const uint32_t aLoAddr = aHiAddr + OFF_ALO;
    const uint32_t bHiAddr = sbase + OFF_BHI + (uint32_t)((lane & 15) * 176 + ((lane >> 4) * 8) * 2);
    const uint32_t bLoAddr = bHiAddr + (OFF_BLO - OFF_BHI);

    float acc[10][4];
    #pragma unroll
    for (int nt = 0; nt < 10; nt++)
        #pragma unroll
        for (int i = 0; i < 4; i++) acc[nt][i] = 0.f;

    for (int chunk = 0; chunk < NCHUNK; chunk++) {
        const int ko = chunk * KC;
        // ---- stage A: x[128 tok x 32 k] fp32 -> bf16 hi/lo ----
        #pragma unroll
        for (int i = 0; i < 4; i++) {
            int idx = tid + i * 256;            // 0..1023 float4s
            int tok = idx >> 3;                 // 8 float4 per 32-float row
            int k4  = (idx & 7) << 2;
            float4 v = *reinterpret_cast<const float4*>(xrow + (size_t)tok * EMB + ko + k4);
            uint32_t h0, l0, h1, l1;
            split_pack(v.x, v.y, h0, l0);
            split_pack(v.z, v.w, h1, l1);
            uint32_t off = (uint32_t)(tok * 80 + k4 * 2);
            *reinterpret_cast<uint2*>(smc + off)           = make_uint2(h0, h1);
            *reinterpret_cast<uint2*>(smc + OFF_ALO + off) = make_uint2(l0, l1);
        }
        // ---- stage B: W[32 k x 80 j] bf16 hi/lo (coalesced u32 copies) ----
        #pragma unroll
        for (int i = 0; i < 5; i++) {
            int idx = tid + i * 256;            // 0..1279 u32
            int k  = idx / 40;
            int jp = idx - k * 40;              // u32 col (2 bf16)
            uint32_t dst = (uint32_t)(k * 176 + jp * 4);
            size_t   src = (size_t)(ko + k) * NJ + 2 * jp;
            *reinterpret_cast<uint32_t*>(smc + OFF_BHI + dst) =
                *reinterpret_cast<const uint32_t*>(&g_WBh[src]);
            *reinterpret_cast<uint32_t*>(smc + OFF_BLO + dst) =
                *reinterpret_cast<const uint32_t*>(&g_WBl[src]);
        }
        __syncthreads();

        // ---- compute: 2 k-steps of 16, 10 n-tiles, 3 terms ----
        #pragma unroll
        for (int ks = 0; ks < 2; ks++) {
            uint32_t Ah[4], Al[4];
            ldsm_x4(Ah, aHiAddr + ks * 32);     // +16 bf16 in k
            ldsm_x4(Al, aLoAddr + ks * 32);
            #pragma unroll
            for (int np = 0; np < 5; np++) {    // each x4 covers 2 n-tiles
                uint32_t Bh[4], Bl[4];
                ldsm_x4_t(Bh, bHiAddr + ks * 2816 + np * 32);
                ldsm_x4_t(Bl, bLoAddr + ks * 2816 + np * 32);
                mma_bf16(acc[2*np],     Ah, Bh + 0);
                mma_bf16(acc[2*np],     Ah, Bl + 0);
                mma_bf16(acc[2*np],     Al, Bh + 0);
                mma_bf16(acc[2*np + 1], Ah, Bh + 2);
                mma_bf16(acc[2*np + 1], Ah, Bl + 2);
                mma_bf16(acc[2*np + 1], Al, Bh + 2);
            }
        }
        __syncthreads();
    }

    // ---- store C frags + bias to res[tok][82] ----
    {
        int r0 = 16 * w + (lane >> 2);
        #pragma unroll
        for (int nt = 0; nt < 10; nt++) {
            int col = nt * 8 + 2 * (lane & 3);
            float b0 = g_bias[col], b1 = g_bias[col + 1];
            *reinterpret_cast<float2*>(&sm.res[r0][col]) =
                make_float2(acc[nt][0] + b0, acc[nt][1] + b1);
            *reinterpret_cast<float2*>(&sm.res[r0 + 8][col]) =
                make_float2(acc[nt][2] + b0, acc[nt][3] + b1);
        }
    }
    __syncthreads();

    const int t0 = tile * TM;
    // flush raw p_q (cols 0..7), coalesced
    #pragma unroll
    for (int i = 0; i < 4; i++) {
        int idx = tid + i * 256;                // tok*8 + m
        int tok = idx >> 3;
        int mq  = idx & 7;
        g_pq[(size_t)t0 * MF + idx] = sm.res[tok][mq];
    }
    __syncthreads();
    // Kp = [cos(p_k), sin(p_k)]/sqrt(m) in place: cos -> 0..7, sin -> 8..15
    #pragma unroll
    for (int i = 0; i < 4; i++) {
        int idx = tid + i * 256;
        int tok = idx >> 3;
        int mm  = idx & 7;
        float p = sm.res[tok][MF + mm];
        float sv, cv;
        sincosf(p, &sv, &cv);
        sm.res[tok][mm]      = cv * INV_SQRT_M;
        sm.res[tok][MF + mm] = sv * INV_SQRT_M;
    }
    __syncthreads();
    // partial S[16][64] for this tile (deterministic, per-tile slab)
    const int d  = tid & 63;
    const int fg = tid >> 6;
    float sacc[4] = {0.f, 0.f, 0.f, 0.f};
    for (int tok = 0; tok < TM; tok++) {
        const float* rr = sm.res[tok];
        float v = rr[2 * MF + d];
        #pragma unroll
        for (int ff = 0; ff < 4; ff++)
            sacc[ff] = fmaf(rr[fg * 4 + ff], v, sacc[ff]);
    }
    float* Sp = g_Spart + (size_t)tile * (NFEAT * DH);
    #pragma unroll
    for (int ff = 0; ff < 4; ff++)
        Sp[(fg * 4 + ff) * DH + d] = sacc[ff];
}

// ============================================================
// reduce: S[b][f][d] = sum over 64 tiles (deterministic order)
// ============================================================
__global__ void reduce_kernel() {
    int g  = blockIdx.x * blockDim.x + threadIdx.x;   // 0..4095
    int b  = g >> 10;
    int fd = g & 1023;
    const float* bs = g_Spart + (size_t)b * 64 * (NFEAT * DH) + fd;
    float s = 0.f;
    #pragma unroll
    for (int tt = 0; tt < 64; tt++) s += bs[(size_t)tt * (NFEAT * DH)];
    g_S[g] = s;
}

// ============================================================
// phase 2: y[t][d] = sum_f qP[t][f] * S[b][f][d]
// 2 threads per token (32 d each) -> lower regs, higher occupancy
// ============================================================
__global__ __launch_bounds__(256) void phase2_kernel(float* __restrict__ y) {
    __shared__ float Ss[NFEAT * DH];
    const int tid = threadIdx.x;
    const int t0  = blockIdx.x * 128;           // 128 tokens per block
    const int b   = t0 / TLEN;

    #pragma unroll
    for (int i = 0; i < 4; i++) Ss[tid + i * 256] = g_S[b * (NFEAT * DH) + tid + i * 256];
    __syncthreads();

    const int tokl = tid >> 1;
    const int half = tid & 1;
    const int t    = t0 + tokl;

    const float* pq = g_pq + (size_t)t * MF;
    float4 pa = *reinterpret_cast<const float4*>(pq);
    float4 pb = *reinterpret_cast<const float4*>(pq + 4);
    float pv[8] = {pa.x, pa.y, pa.z, pa.w, pb.x, pb.y, pb.z, pb.w};
    float q[NFEAT];
    #pragma unroll
    for (int m2 = 0; m2 < 8; m2++) {
        float sv, cv;
        sincosf(pv[m2], &sv, &cv);
        q[m2]     = cv * INV_SQRT_M;
        q[8 + m2] = sv * INV_SQRT_M;
    }

    float out[32];
    #pragma unroll
    for (int d = 0; d < 32; d++) out[d] = 0.f;

    const float* Sp = Ss + half * 32;
    #pragma unroll
    for (int f = 0; f < NFEAT; f++) {
        float qf = q[f];
        const float4* row = reinterpret_cast<const float4*>(Sp + f * DH);
        #pragma unroll
        for (int j = 0; j < 8; j++) {
            float4 sv = row[j];
            out[4*j + 0] = fmaf(qf, sv.x, out[4*j + 0]);
            out[4*j + 1] = fmaf(qf, sv.y, out[4*j + 1]);
            out[4*j + 2] = fmaf(qf, sv.z, out[4*j + 2]);
            out[4*j + 3] = fmaf(qf, sv.w, out[4*j + 3]);
        }
    }

    float4* yo = reinterpret_cast<float4*>(y + (size_t)t * DH + half * 32);
    #pragma unroll
    for (int j = 0; j < 8; j++)
        yo[j] = make_float4(out[4*j], out[4*j + 1], out[4*j + 2], out[4*j + 3]);
}

// ============================================================
extern "C" void kernel_launch(void* const* d_in, const int* in_sizes, int n_in,
                              void* d_out, int out_size) {
    (void)in_sizes; (void)n_in; (void)out_size;
    const float* x  = (const float*)d_in[0];
    const float* w  = (const float*)d_in[1];
    const float* Wq = (const float*)d_in[2];
    const float* bq = (const float*)d_in[3];
    const float* Wk = (const float*)d_in[4];
    const float* bk = (const float*)d_in[5];
    const float* Wv = (const float*)d_in[6];
    const float* bv = (const float*)d_in[7];
    float* y = (float*)d_out;

    prep_kernel<<<(EMB * NJ + 255) / 256, 256>>>(w, Wq, bq, Wk, bk, Wv, bv);
    phase1_kernel<<<NTILE, 256>>>(x);
    reduce_kernel<<<(BATCH * NFEAT * DH) / 256, 256>>>();
    phase2_kernel<<<(BATCH * TLEN) / 128, 256>>>(y);
}

// round 9
// speedup vs baseline: 2.4450x; 1.0663x over previous
#include <cuda_runtime.h>
#include <cuda_bf16.h>
#include <math.h>
#include <stdint.h>

// Problem constants
#define BATCH 4
#define TLEN  8192
#define EMB   1024
#define DH    64
#define MF    8
#define NJ    80          // 8 p_q + 8 p_k + 64 v
#define TM    128         // tokens per phase-1 tile (MMA M)
#define KC    32          // K per staged chunk (bf16)
#define NCHUNK (EMB/KC)   // 32
#define NTILE ((BATCH*TLEN)/TM)   // 256
#define NFEAT (2*MF)
#define INV_SQRT_M 0.35355339059327376f

// ---- device scratch (no allocations allowed) ----
__device__ __nv_bfloat16 g_WBh[EMB*NJ];   // folded W [e][j] bf16 hi
__device__ __nv_bfloat16 g_WBl[EMB*NJ];   // bf16 lo residual
__device__ float g_bias[NJ];
__device__ float g_qP[BATCH*TLEN*NFEAT];  // finished q features (2 MB)
__device__ float g_Spart[NTILE*NFEAT*DH];
__device__ float g_S[BATCH*NFEAT*DH];

// ---- smem layout: 2 pipeline stages ----
#define OFF_ALO 10240
#define OFF_BHI 20480
#define OFF_BLO 26112
#define STAGE_BYTES 31744
#define DYN_BYTES (2 * STAGE_BYTES)   // 63488; res[128][82] (41984) aliases offset 0

// ---- helpers ----
__device__ __forceinline__ uint32_t smem_u32(const void* p) {
    uint32_t a;
    asm("{ .reg .u64 t; cvta.to.shared.u64 t, %1; cvt.u32.u64 %0, t; }" : "=r"(a) : "l"(p));
    return a;
}
__device__ __forceinline__ void ldsm_x4(uint32_t* r, uint32_t addr) {
    asm volatile("ldmatrix.sync.aligned.m8n8.x4.shared.b16 {%0,%1,%2,%3}, [%4];"
        : "=r"(r[0]), "=r"(r[1]), "=r"(r[2]), "=r"(r[3]) : "r"(addr));
}
__device__ __forceinline__ void ldsm_x4_t(uint32_t* r, uint32_t addr) {
    asm volatile("ldmatrix.sync.aligned.m8n8.x4.trans.shared.b16 {%0,%1,%2,%3}, [%4];"
        : "=r"(r[0]), "=r"(r[1]), "=r"(r[2]), "=r"(r[3]) : "r"(addr));
}
__device__ __forceinline__ void mma_bf16(float* c, const uint32_t* a, const uint32_t* b) {
    asm volatile("mma.sync.aligned.m16n8k16.row.col.f32.bf16.bf16.f32 "
        "{%0,%1,%2,%3}, {%4,%5,%6,%7}, {%8,%9}, {%0,%1,%2,%3};"
        : "+f"(c[0]), "+f"(c[1]), "+f"(c[2]), "+f"(c[3])
        : "r"(a[0]), "r"(a[1]), "r"(a[2]), "r"(a[3]), "r"(b[0]), "r"(b[1]));
}
__device__ __forceinline__ void split_pack(float vx, float vy, uint32_t& hi, uint32_t& lo) {
    __nv_bfloat162 h = __float22bfloat162_rn(make_float2(vx, vy));
    float2 hf = __bfloat1622float2(h);
    __nv_bfloat162 l = __float22bfloat162_rn(make_float2(vx - hf.x, vy - hf.y));
    hi = *reinterpret_cast<uint32_t*>(&h);
    lo = *reinterpret_cast<uint32_t*>(&l);
}

// ============================================================
// prep: fold Wq@w, Wk@w + Wv into bf16 hi/lo [e][j]; biases.
// ============================================================
__global__ void prep_kernel(const float* __restrict__ w,
                            const float* __restrict__ Wq, const float* __restrict__ bq,
                            const float* __restrict__ Wk, const float* __restrict__ bk,
                            const float* __restrict__ Wv, const float* __restrict__ bv) {
    int g = blockIdx.x * blockDim.x + threadIdx.x;
    if (g < NJ) {
        float bb;
        if (g < MF) {
            bb = 0.f;
            for (int d = 0; d < DH; d++) bb += bq[d] * w[d*MF + g];
        } else if (g < 2*MF) {
            int jj = g - MF;
            bb = 0.f;
            for (int d = 0; d < DH; d++) bb += bk[d] * w[d*MF + jj];
        } else {
            bb = bv[g - 2*MF];
        }
        g_bias[g] = bb;
    }
    if (g >= EMB*NJ) return;
    int e = g / NJ;
    int j = g - e*NJ;
    float val;
    if (j < MF) {
        val = 0.f;
        for (int d = 0; d < DH; d++) val += Wq[e*DH + d] * w[d*MF + j];
    } else if (j < 2*MF) {
        int jj = j - MF;
        val = 0.f;
        for (int d = 0; d < DH; d++) val += Wk[e*DH + d] * w[d*MF + jj];
    } else {
        val = Wv[e*DH + (j - 2*MF)];
    }
    __nv_bfloat16 h = __float2bfloat16(val);
    float lo = val - __bfloat162float(h);
    g_WBh[g] = h;
    g_WBl[g] = __float2bfloat16(lo);
}

// ============================================================
// phase 1: pipelined HMMA bf16 3-term GEMM [128 x 80] + epilogue
// ============================================================
__global__ __launch_bounds__(256, 2) void phase1_kernel(const float* __restrict__ x) {
    extern __shared__ char smc[];
    const int tid  = threadIdx.x;
    const int lane = tid & 31;
    const int w    = tid >> 5;                 // warp 0..7 -> M rows 16w..16w+15
    const int tile = blockIdx.x;
    const float* xrow = x + (size_t)tile * TM * EMB;
    const uint32_t sbase = smem_u32(smc);

    // per-lane ldmatrix offsets (within a stage)
    const uint32_t aOffHi = (uint32_t)((16*w + (lane & 15)) * 80 + ((lane >> 4) * 8) * 2);
    const uint32_t bOffHi = (uint32_t)(OFF_BHI + (lane & 15) * 176 + ((lane >> 4) * 8) * 2);

    // staging index precompute
    const int sa_tok = tid >> 3;               // A: token for idx=tid (i term adds 32)
    const int sa_k4  = (tid & 7) << 2;

    float acc[10][4];
    #pragma unroll
    for (int nt = 0; nt < 10; nt++)
        #pragma unroll
        for (int i = 0; i < 4; i++) acc[nt][i] = 0.f;

    // ---- prologue: stage chunk 0 into stage 0 ----
    {
        char* sb = smc;
        #pragma unroll
        for (int i = 0; i < 4; i++) {
            int tok = sa_tok + i * 32;
            float4 v = *reinterpret_cast<const float4*>(xrow + (size_t)tok * EMB + sa_k4);
            uint32_t h0, l0, h1, l1;
            split_pack(v.x, v.y, h0, l0);
            split_pack(v.z, v.w, h1, l1);
            uint32_t off = (uint32_t)(tok * 80 + sa_k4 * 2);
            *reinterpret_cast<uint2*>(sb + off)           = make_uint2(h0, h1);
            *reinterpret_cast<uint2*>(sb + OFF_ALO + off) = make_uint2(l0, l1);
        }
        #pragma unroll
        for (int i = 0; i < 5; i++) {
            int idx = tid + i * 256;
            int k  = idx / 40;
            int jp = idx - k * 40;
            uint32_t dst = (uint32_t)(k * 176 + jp * 4);
            size_t   src = (size_t)k * NJ + 2 * jp;     // u32-granular: elem idx 2*jp
            *reinterpret_cast<uint32_t*>(sb + OFF_BHI + dst) =
                *reinterpret_cast<const uint32_t*>(&g_WBh[src]);
            *reinterpret_cast<uint32_t*>(sb + OFF_BLO + dst) =
                *reinterpret_cast<const uint32_t*>(&g_WBl[src]);
        }
    }
    __syncthreads();

    // ---- pipelined main loop ----
    for (int c = 0; c < NCHUNK; c++) {
        const uint32_t sOff = (uint32_t)((c & 1) * STAGE_BYTES);
        const int nxt = c + 1;

        // 1) prefetch chunk c+1 into registers (independent of compute)
        float4 va[4];
        uint32_t wh[5], wl[5];
        if (nxt < NCHUNK) {
            const int ko = nxt * KC;
            #pragma unroll
            for (int i = 0; i < 4; i++) {
                int tok = sa_tok + i * 32;
                va[i] = *reinterpret_cast<const float4*>(xrow + (size_t)tok * EMB + ko + sa_k4);
            }
            #pragma unroll
            for (int i = 0; i < 5; i++) {
                int idx = tid + i * 256;
                int k  = idx / 40;
                int jp = idx - k * 40;
                size_t src = (size_t)(ko + k) * NJ + 2 * jp;
                wh[i] = *reinterpret_cast<const uint32_t*>(&g_WBh[src]);
                wl[i] = *reinterpret_cast<const uint32_t*>(&g_WBl[src]);
            }
        }

        // 2) compute chunk c from stage (c&1)
        const uint32_t aHiAddr = sbase + sOff + aOffHi;
        const uint32_t aLoAddr = aHiAddr + OFF_ALO;
        const uint32_t bHiAddr = sbase + sOff + bOffHi;
        const uint32_t bLoAddr = bHiAddr + (OFF_BLO - OFF_BHI);
        #pragma unroll
        for (int ks = 0; ks < 2; ks++) {
            uint32_t Ah[4], Al[4];
            ldsm_x4(Ah, aHiAddr + ks * 32);
            ldsm_x4(Al, aLoAddr + ks * 32);
            #pragma unroll
            for (int np = 0; np < 5; np++) {
                uint32_t Bh[4], Bl[4];
                ldsm_x4_t(Bh, bHiAddr + ks * 2816 + np * 32);
                ldsm_x4_t(Bl, bLoAddr + ks * 2816 + np * 32);
                mma_bf16(acc[2*np],     Ah, Bh + 0);
                mma_bf16(acc[2*np],     Ah, Bl + 0);
                mma_bf16(acc[2*np],     Al, Bh + 0);
                mma_bf16(acc[2*np + 1], Ah, Bh + 2);
                mma_bf16(acc[2*np + 1], Ah, Bl + 2);
                mma_bf16(acc[2*np + 1], Al, Bh + 2);
            }
        }

        // 3) convert + store chunk c+1 into stage ((c+1)&1)
        if (nxt < NCHUNK) {
            char* sb = smc + (nxt & 1) * STAGE_BYTES;
            #pragma unroll
            for (int i = 0; i < 4; i++) {
                int tok = sa_tok + i * 32;
                uint32_t h0, l0, h1, l1;
                split_pack(va[i].x, va[i].y, h0, l0);
                split_pack(va[i].z, va[i].w, h1, l1);
                uint32_t off = (uint32_t)(tok * 80 + sa_k4 * 2);
                *reinterpret_cast<uint2*>(sb + off)           = make_uint2(h0, h1);
                *reinterpret_cast<uint2*>(sb + OFF_ALO + off) = make_uint2(l0, l1);
            }
            #pragma unroll
            for (int i = 0; i < 5; i++) {
                int idx = tid + i * 256;
                int k  = idx / 40;
                int jp = idx - k * 40;
                uint32_t dst = (uint32_t)(k * 176 + jp * 4);
                *reinterpret_cast<uint32_t*>(sb + OFF_BHI + dst) = wh[i];
                *reinterpret_cast<uint32_t*>(sb + OFF_BLO + dst) = wl[i];
            }
        }
        __syncthreads();
    }

    // ---- epilogue: C frags + bias -> res[tok][82] (aliases stage smem) ----
    float (*res)[82] = reinterpret_cast<float (*)[82]>(smc);
    {
        int r0 = 16 * w + (lane >> 2);
        #pragma unroll
        for (int nt = 0; nt < 10; nt++) {
            int col = nt * 8 + 2 * (lane & 3);
            float b0 = g_bias[col], b1 = g_bias[col + 1];
            *reinterpret_cast<float2*>(&res[r0][col]) =
                make_float2(acc[nt][0] + b0, acc[nt][1] + b1);
            *reinterpret_cast<float2*>(&res[r0 + 8][col]) =
                make_float2(acc[nt][2] + b0, acc[nt][3] + b1);
        }
    }
    __syncthreads();

    const int t0 = tile * TM;
    // q-path: sincos here, store finished qP (cos 0..7 | sin 8..15)
    #pragma unroll
    for (int i = 0; i < 4; i++) {
        int idx = tid + i * 256;                // tok*8 + m
        int tok = idx >> 3;
        int mq  = idx & 7;
        float p = res[tok][mq];
        float sv, cv;
        sincosf(p, &sv, &cv);
        float* qp = g_qP + (size_t)(t0 + tok) * NFEAT;
        qp[mq]      = cv * INV_SQRT_M;
        qp[MF + mq] = sv * INV_SQRT_M;
    }
    __syncthreads();
    // k-path: Kp in place: cos -> 0..7, sin -> 8..15
    #pragma unroll
    for (int i = 0; i < 4; i++) {
        int idx = tid + i * 256;
        int tok = idx >> 3;
        int mm  = idx & 7;
        float p = res[tok][MF + mm];
        float sv, cv;
        sincosf(p, &sv, &cv);
        res[tok][mm]      = cv * INV_SQRT_M;
        res[tok][MF + mm] = sv * INV_SQRT_M;
    }
    __syncthreads();
    // partial S[16][64] for this tile (deterministic per-tile slab)
    const int d  = tid & 63;
    const int fg = tid >> 6;
    float sacc[4] = {0.f, 0.f, 0.f, 0.f};
    for (int tok = 0; tok < TM; tok++) {
        const float* rr = res[tok];
        float v = rr[2 * MF + d];
        #pragma unroll
        for (int ff = 0; ff < 4; ff++)
            sacc[ff] = fmaf(rr[fg * 4 + ff], v, sacc[ff]);
    }
    float* Sp = g_Spart + (size_t)tile * (NFEAT * DH);
    #pragma unroll
    for (int ff = 0; ff < 4; ff++)
        Sp[(fg * 4 + ff) * DH + d] = sacc[ff];
}

// ============================================================
// reduce: S[b][f][d] = sum over 64 tiles (deterministic order)
// ============================================================
__global__ void reduce_kernel() {
    int g  = blockIdx.x * blockDim.x + threadIdx.x;   // 0..4095
    int b  = g >> 10;
    int fd = g & 1023;
    const float* bs = g_Spart + (size_t)b * 64 * (NFEAT * DH) + fd;
    float s = 0.f;
    #pragma unroll
    for (int tt = 0; tt < 64; tt++) s += bs[(size_t)tt * (NFEAT * DH)];
    g_S[g] = s;
}

// ============================================================
// phase 2: y[t][d] = sum_f qP[t][f] * S[b][f][d]
// 4 threads/token (16 d each), qP precomputed -> pure streaming
// ============================================================
__global__ __launch_bounds__(256) void phase2_kernel(float* __restrict__ y) {
    __shared__ float Ss[NFEAT * DH];
    const int tid = threadIdx.x;
    const int t0  = blockIdx.x * 64;            // 64 tokens per block
    const int b   = t0 / TLEN;

    #pragma unroll
    for (int i = 0; i < 4; i++) Ss[tid + i * 256] = g_S[b * (NFEAT * DH) + tid + i * 256];
    __syncthreads();

    const int tokl = tid >> 2;
    const int qtr  = tid & 3;
    const int t    = t0 + tokl;

    float q[NFEAT];
    const float4* qp = reinterpret_cast<const float4*>(g_qP + (size_t)t * NFEAT);
    #pragma unroll
    for (int i = 0; i < 4; i++) {
        float4 v = qp[i];
        q[4*i + 0] = v.x; q[4*i + 1] = v.y; q[4*i + 2] = v.z; q[4*i + 3] = v.w;
    }

    float out[16];
    #pragma unroll
    for (int d = 0; d < 16; d++) out[d] = 0.f;

    const float* Sp = Ss + qtr * 16;
    #pragma unroll
    for (int f = 0; f < NFEAT; f++) {
        float qf = q[f];
        const float4* row = reinterpret_cast<const float4*>(Sp + f * DH);
        #pragma unroll
        for (int j = 0; j < 4; j++) {
            float4 sv = row[j];
            out[4*j + 0] = fmaf(qf, sv.x, out[4*j + 0]);
            out[4*j + 1] = fmaf(qf, sv.y, out[4*j + 1]);
            out[4*j + 2] = fmaf(qf, sv.z, out[4*j + 2]);
            out[4*j + 3] = fmaf(qf, sv.w, out[4*j + 3]);
        }
    }

    float4* yo = reinterpret_cast<float4*>(y + (size_t)t * DH + qtr * 16);
    #pragma unroll
    for (int j = 0; j < 4; j++)
        yo[j] = make_float4(out[4*j], out[4*j + 1], out[4*j + 2], out[4*j + 3]);
}

// ============================================================
extern "C" void kernel_launch(void* const* d_in, const int* in_sizes, int n_in,
                              void* d_out, int out_size) {
    (void)in_sizes; (void)n_in; (void)out_size;
    const float* x  = (const float*)d_in[0];
    const float* w  = (const float*)d_in[1];
    const float* Wq = (const float*)d_in[2];
    const float* bq = (const float*)d_in[3];
    const float* Wk = (const float*)d_in[4];
    const float* bk = (const float*)d_in[5];
    const float* Wv = (const float*)d_in[6];
    const float* bv = (const float*)d_in[7];
    float* y = (float*)d_out;

    static int attr_set = 0;
    if (!attr_set) {
        cudaFuncSetAttribute(phase1_kernel, cudaFuncAttributeMaxDynamicSharedMemorySize, DYN_BYTES);
        attr_set = 1;
    }

    prep_kernel<<<(EMB * NJ + 255) / 256, 256>>>(w, Wq, bq, Wk, bk, Wv, bv);
    phase1_kernel<<<NTILE, 256, DYN_BYTES>>>(x);
    reduce_kernel<<<(BATCH * NFEAT * DH) / 256, 256>>>();
    phase2_kernel<<<(BATCH * TLEN) / 64, 256>>>(y);
}

// round 10
// speedup vs baseline: 3.3114x; 1.3543x over previous
#include <cuda_runtime.h>
#include <cuda_fp16.h>
#include <math.h>
#include <stdint.h>

// Problem constants
#define BATCH 4
#define TLEN  8192
#define EMB   1024
#define DH    64
#define MF    8
#define NJ    80          // 8 p_q + 8 p_k + 64 v
#define TM    128         // tokens per phase-1 tile (MMA M)
#define KC    32          // K per staged chunk
#define NCHUNK (EMB/KC)   // 32
#define NTILE ((BATCH*TLEN)/TM)   // 256
#define NFEAT (2*MF)
#define INV_SQRT_M 0.35355339059327376f

// ---- device scratch (no allocations allowed) ----
__device__ __half g_WBh[EMB*NJ];          // folded W [e][j] fp16 hi (all 80 cols)
__device__ __half g_WBl[EMB*NJ];          // fp16 lo residual (used for cols 0..15)
__device__ float g_bias[NJ];
__device__ float g_qP[BATCH*TLEN*NFEAT];  // finished q features (2 MB)
__device__ float g_Spart[NTILE*NFEAT*DH];
__device__ float g_S[BATCH*NFEAT*DH];

// ---- smem stage layout ----
#define OFF_ALO 10240      // a_hi[128][40] fp16 = 10240 B
#define OFF_BHI 20480      // a_lo same size
#define OFF_BLO 26112      // b_hi[32][88] fp16 = 5632 B
#define STAGE_BYTES 27648  // b_lo[32][24] fp16 = 1536 B
#define DYN_BYTES (2 * STAGE_BYTES)   // 55296; res[128][82] (41984) aliases offset 0

// ---- helpers ----
__device__ __forceinline__ uint32_t smem_u32(const void* p) {
    uint32_t a;
    asm("{ .reg .u64 t; cvta.to.shared.u64 t, %1; cvt.u32.u64 %0, t; }" : "=r"(a) : "l"(p));
    return a;
}
__device__ __forceinline__ void ldsm_x4(uint32_t* r, uint32_t addr) {
    asm volatile("ldmatrix.sync.aligned.m8n8.x4.shared.b16 {%0,%1,%2,%3}, [%4];"
        : "=r"(r[0]), "=r"(r[1]), "=r"(r[2]), "=r"(r[3]) : "r"(addr));
}
__device__ __forceinline__ void ldsm_x4_t(uint32_t* r, uint32_t addr) {
    asm volatile("ldmatrix.sync.aligned.m8n8.x4.trans.shared.b16 {%0,%1,%2,%3}, [%4];"
        : "=r"(r[0]), "=r"(r[1]), "=r"(r[2]), "=r"(r[3]) : "r"(addr));
}
__device__ __forceinline__ void mma_f16(float* c, const uint32_t* a, const uint32_t* b) {
    asm volatile("mma.sync.aligned.m16n8k16.row.col.f32.f16.f16.f32 "
        "{%0,%1,%2,%3}, {%4,%5,%6,%7}, {%8,%9}, {%0,%1,%2,%3};"
        : "+f"(c[0]), "+f"(c[1]), "+f"(c[2]), "+f"(c[3])
        : "r"(a[0]), "r"(a[1]), "r"(a[2]), "r"(a[3]), "r"(b[0]), "r"(b[1]));
}
// split fp32 pair -> packed fp16 hi + fp16 lo(residual)
__device__ __forceinline__ void split_pack(float vx, float vy, uint32_t& hi, uint32_t& lo) {
    __half2 h = __floats2half2_rn(vx, vy);
    float2 hf = __half22float2(h);
    __half2 l = __floats2half2_rn(vx - hf.x, vy - hf.y);
    hi = *reinterpret_cast<uint32_t*>(&h);
    lo = *reinterpret_cast<uint32_t*>(&l);
}

// ============================================================
// prep: fold Wq@w, Wk@w + Wv into fp16 hi/lo [e][j]; biases.
// ============================================================
__global__ void prep_kernel(const float* __restrict__ w,
                            const float* __restrict__ Wq, const float* __restrict__ bq,
                            const float* __restrict__ Wk, const float* __restrict__ bk,
                            const float* __restrict__ Wv, const float* __restrict__ bv) {
    int g = blockIdx.x * blockDim.x + threadIdx.x;
    if (g < NJ) {
        float bb;
        if (g < MF) {
            bb = 0.f;
            for (int d = 0; d < DH; d++) bb += bq[d] * w[d*MF + g];
        } else if (g < 2*MF) {
            int jj = g - MF;
            bb = 0.f;
            for (int d = 0; d < DH; d++) bb += bk[d] * w[d*MF + jj];
        } else {
            bb = bv[g - 2*MF];
        }
        g_bias[g] = bb;
    }
    if (g >= EMB*NJ) return;
    int e = g / NJ;
    int j = g - e*NJ;
    float val;
    if (j < MF) {
        val = 0.f;
        for (int d = 0; d < DH; d++) val += Wq[e*DH + d] * w[d*MF + j];
    } else if (j < 2*MF) {
        int jj = j - MF;
        val = 0.f;
        for (int d = 0; d < DH; d++) val += Wk[e*DH + d] * w[d*MF + jj];
    } else {
        val = Wv[e*DH + (j - 2*MF)];
    }
    __half h = __float2half_rn(val);
    g_WBh[g] = h;
    g_WBl[g] = __float2half_rn(val - __half2float(h));
}

// ============================================================
// phase 1: pipelined HMMA fp16 GEMM [128 x 80]
//   p-cols (0..15): 3-term split; v-cols (16..79): 2-term
// ============================================================
__global__ __launch_bounds__(256, 2) void phase1_kernel(const float* __restrict__ x) {
    extern __shared__ char smc[];
    const int tid  = threadIdx.x;
    const int lane = tid & 31;
    const int w    = tid >> 5;                 // warp 0..7 -> M rows 16w..16w+15
    const int tile = blockIdx.x;
    const float* xrow = x + (size_t)tile * TM * EMB;
    const uint32_t sbase = smem_u32(smc);

    // per-lane ldmatrix offsets (within a stage)
    const uint32_t aOffHi = (uint32_t)((16*w + (lane & 15)) * 80 + ((lane >> 4) * 8) * 2);
    const uint32_t bOffHi = (uint32_t)(OFF_BHI + (lane & 15) * 176 + ((lane >> 4) * 8) * 2);
    const uint32_t bOffLo = (uint32_t)(OFF_BLO + (lane & 15) * 48  + ((lane >> 4) * 8) * 2);

    // staging index precompute
    const int sa_tok = tid >> 3;               // A: token (i term adds 32)
    const int sa_k4  = (tid & 7) << 2;
    const int sb_k   = tid / 40;               // B hi: k row (tid<..); 5 iters of 256
    const int sb_jp  = tid - sb_k * 40;
    const int sl_k   = tid >> 3;               // B lo: k row 0..31
    const int sl_jp  = tid & 7;                // u32 col 0..7 (fp16 cols 0..15)

    float acc[10][4];
    #pragma unroll
    for (int nt = 0; nt < 10; nt++)
        #pragma unroll
        for (int i = 0; i < 4; i++) acc[nt][i] = 0.f;

    // ---- prologue: stage chunk 0 into stage 0 ----
    {
        char* sb = smc;
        #pragma unroll
        for (int i = 0; i < 4; i++) {
            int tok = sa_tok + i * 32;
            float4 v = *reinterpret_cast<const float4*>(xrow + (size_t)tok * EMB + sa_k4);
            uint32_t h0, l0, h1, l1;
            split_pack(v.x, v.y, h0, l0);
            split_pack(v.z, v.w, h1, l1);
            uint32_t off = (uint32_t)(tok * 80 + sa_k4 * 2);
            *reinterpret_cast<uint2*>(sb + off)           = make_uint2(h0, h1);
            *reinterpret_cast<uint2*>(sb + OFF_ALO + off) = make_uint2(l0, l1);
        }
        #pragma unroll
        for (int i = 0; i < 5; i++) {
            int idx = tid + i * 256;
            int k  = idx / 40;
            int jp = idx - k * 40;
            *reinterpret_cast<uint32_t*>(sb + OFF_BHI + k * 176 + jp * 4) =
                *reinterpret_cast<const uint32_t*>(&g_WBh[(size_t)k * NJ + 2 * jp]);
        }
        *reinterpret_cast<uint32_t*>(sb + OFF_BLO + sl_k * 48 + sl_jp * 4) =
            *reinterpret_cast<const uint32_t*>(&g_WBl[(size_t)sl_k * NJ + 2 * sl_jp]);
    }
    __syncthreads();

    // ---- pipelined main loop ----
    for (int c = 0; c < NCHUNK; c++) {
        const uint32_t sOff = (uint32_t)((c & 1) * STAGE_BYTES);
        const int nxt = c + 1;

        // 1) prefetch chunk c+1 into registers
        float4 va[4];
        uint32_t wh[5], wl0;
        if (nxt < NCHUNK) {
            const int ko = nxt * KC;
            #pragma unroll
            for (int i = 0; i < 4; i++) {
                int tok = sa_tok + i * 32;
                va[i] = *reinterpret_cast<const float4*>(xrow + (size_t)tok * EMB + ko + sa_k4);
            }
            #pragma unroll
            for (int i = 0; i < 5; i++) {
                int idx = tid + i * 256;
                int k  = idx / 40;
                int jp = idx - k * 40;
                wh[i] = *reinterpret_cast<const uint32_t*>(&g_WBh[(size_t)(ko + k) * NJ + 2 * jp]);
            }
            wl0 = *reinterpret_cast<const uint32_t*>(&g_WBl[(size_t)(ko + sl_k) * NJ + 2 * sl_jp]);
        }

        // 2) compute chunk c from stage (c&1)
        const uint32_t aHiAddr = sbase + sOff + aOffHi;
        const uint32_t aLoAddr = aHiAddr + OFF_ALO;
        const uint32_t bHiAddr = sbase + sOff + bOffHi;
        const uint32_t bLoAddr = sbase + sOff + bOffLo;
        #pragma unroll
        for (int ks = 0; ks < 2; ks++) {
            uint32_t Ah[4], Al[4];
            ldsm_x4(Ah, aHiAddr + ks * 32);
            ldsm_x4(Al, aLoAddr + ks * 32);
            // np = 0 : p-columns 0..15, 3-term
            {
                uint32_t Bh[4], Bl[4];
                ldsm_x4_t(Bh, bHiAddr + ks * 2816);
                ldsm_x4_t(Bl, bLoAddr + ks * 768);
                mma_f16(acc[0], Ah, Bh + 0);
                mma_f16(acc[1], Ah, Bh + 2);
                mma_f16(acc[0], Ah, Bl + 0);
                mma_f16(acc[1], Ah, Bl + 2);
                mma_f16(acc[0], Al, Bh + 0);
                mma_f16(acc[1], Al, Bh + 2);
            }
            // np = 1..4 : v-columns, 2-term
            #pragma unroll
            for (int np = 1; np < 5; np++) {
                uint32_t Bh[4];
                ldsm_x4_t(Bh, bHiAddr + ks * 2816 + np * 32);
                mma_f16(acc[2*np],     Ah, Bh + 0);
                mma_f16(acc[2*np + 1], Ah, Bh + 2);
                mma_f16(acc[2*np],     Al, Bh + 0);
                mma_f16(acc[2*np + 1], Al, Bh + 2);
            }
        }

        // 3) convert + store chunk c+1 into stage ((c+1)&1)
        if (nxt < NCHUNK) {
            char* sb = smc + (nxt & 1) * STAGE_BYTES;
            #pragma unroll
            for (int i = 0; i < 4; i++) {
                int tok = sa_tok + i * 32;
                uint32_t h0, l0, h1, l1;
                split_pack(va[i].x, va[i].y, h0, l0);
                split_pack(va[i].z, va[i].w, h1, l1);
                uint32_t off = (uint32_t)(tok * 80 + sa_k4 * 2);
                *reinterpret_cast<uint2*>(sb + off)           = make_uint2(h0, h1);
                *reinterpret_cast<uint2*>(sb + OFF_ALO + off) = make_uint2(l0, l1);
            }
            #pragma unroll
            for (int i = 0; i < 5; i++) {
                int idx = tid + i * 256;
                int k  = idx / 40;
                int jp = idx - k * 40;
                *reinterpret_cast<uint32_t*>(sb + OFF_BHI + k * 176 + jp * 4) = wh[i];
            }
            *reinterpret_cast<uint32_t*>(sb + OFF_BLO + sl_k * 48 + sl_jp * 4) = wl0;
        }
        __syncthreads();
    }

    // ---- epilogue: C frags + bias -> res[tok][82] (aliases stage smem) ----
    float (*res)[82] = reinterpret_cast<float (*)[82]>(smc);
    {
        int r0 = 16 * w + (lane >> 2);
        #pragma unroll
        for (int nt = 0; nt < 10; nt++) {
            int col = nt * 8 + 2 * (lane & 3);
            float b0 = g_bias[col], b1 = g_bias[col + 1];
            *reinterpret_cast<float2*>(&res[r0][col]) =
                make_float2(acc[nt][0] + b0, acc[nt][1] + b1);
            *reinterpret_cast<float2*>(&res[r0 + 8][col]) =
                make_float2(acc[nt][2] + b0, acc[nt][3] + b1);
        }
    }
    __syncthreads();

    const int t0 = tile * TM;
    // q-path: sincos here, store finished qP (cos 0..7 | sin 8..15)
    #pragma unroll
    for (int i = 0; i < 4; i++) {
        int idx = tid + i * 256;                // tok*8 + m
        int tok = idx >> 3;
        int mq  = idx & 7;
        float p = res[tok][mq];
        float sv, cv;
        sincosf(p, &sv, &cv);
        float* qp = g_qP + (size_t)(t0 + tok) * NFEAT;
        qp[mq]      = cv * INV_SQRT_M;
        qp[MF + mq] = sv * INV_SQRT_M;
    }
    __syncthreads();
    // k-path: Kp in place: cos -> 0..7, sin -> 8..15
    #pragma unroll
    for (int i = 0; i < 4; i++) {
        int idx = tid + i * 256;
        int tok = idx >> 3;
        int mm  = idx & 7;
        float p = res[tok][MF + mm];
        float sv, cv;
        sincosf(p, &sv, &cv);
        res[tok][mm]      = cv * INV_SQRT_M;
        res[tok][MF + mm] = sv * INV_SQRT_M;
    }
    __syncthreads();
    // partial S[16][64] for this tile (deterministic per-tile slab)
    const int d  = tid & 63;
    const int fg = tid >> 6;
    float sacc[4] = {0.f, 0.f, 0.f, 0.f};
    for (int tok = 0; tok < TM; tok++) {
        const float* rr = res[tok];
        float v = rr[2 * MF + d];
        #pragma unroll
        for (int ff = 0; ff < 4; ff++)
            sacc[ff] = fmaf(rr[fg * 4 + ff], v, sacc[ff]);
    }
    float* Sp = g_Spart + (size_t)tile * (NFEAT * DH);
    #pragma unroll
    for (int ff = 0; ff < 4; ff++)
        Sp[(fg * 4 + ff) * DH + d] = sacc[ff];
}

// ============================================================
// reduce: S[b][f][d] = sum over 64 tiles (deterministic order)
// ============================================================
__global__ void reduce_kernel() {
    int g  = blockIdx.x * blockDim.x + threadIdx.x;   // 0..4095
    int b  = g >> 10;
    int fd = g & 1023;
    const float* bs = g_Spart + (size_t)b * 64 * (NFEAT * DH) + fd;
    float s = 0.f;
    #pragma unroll
    for (int tt = 0; tt < 64; tt++) s += bs[(size_t)tt * (NFEAT * DH)];
    g_S[g] = s;
}

// ============================================================
// phase 2: y[t][d] = sum_f qP[t][f] * S[b][f][d]
// lane owns a d-pair (S column pair in regs); warp does 16 tokens
// ============================================================
__global__ __launch_bounds__(256) void phase2_kernel(float* __restrict__ y) {
    __shared__ float Ss[NFEAT * DH];    // 4 KB
    __shared__ float qs[128][20];       // 10 KB (pad 20 keeps float4 stores aligned)
    const int tid  = threadIdx.x;
    const int lane = tid & 31;
    const int wp   = tid >> 5;
    const int t0   = blockIdx.x * 128;  // 128 tokens per block (no batch straddle)
    const int b    = t0 / TLEN;

    #pragma unroll
    for (int i = 0; i < 4; i++) Ss[tid + i * 256] = g_S[b * (NFEAT * DH) + tid + i * 256];
    #pragma unroll
    for (int i = 0; i < 2; i++) {
        int idx = tid + i * 256;        // 0..511 float4s: tok = idx>>2, grp = idx&3
        float4 v = *reinterpret_cast<const float4*>(g_qP + (size_t)t0 * NFEAT + idx * 4);
        *reinterpret_cast<float4*>(&qs[idx >> 2][(idx & 3) * 4]) = v;
    }
    __syncthreads();

    // preload this lane's S column pair (d = 2*lane, 2*lane+1)
    float2 Sreg[NFEAT];
    #pragma unroll
    for (int f = 0; f < NFEAT; f++)
        Sreg[f] = *reinterpret_cast<const float2*>(&Ss[f * DH + 2 * lane]);

    #pragma unroll 4
    for (int it = 0; it < 16; it++) {
        int tok = wp * 16 + it;
        const float4* qv = reinterpret_cast<const float4*>(qs[tok]);   // broadcast reads
        float2 o = make_float2(0.f, 0.f);
        #pragma unroll
        for (int j = 0; j < 4; j++) {
            float4 q4 = qv[j];
            o.x = fmaf(q4.x, Sreg[4*j + 0].x, o.x); o.y = fmaf(q4.x, Sreg[4*j + 0].y, o.y);
            o.x = fmaf(q4.y, Sreg[4*j + 1].x, o.x); o.y = fmaf(q4.y, Sreg[4*j + 1].y, o.y);
            o.x = fmaf(q4.z, Sreg[4*j + 2].x, o.x); o.y = fmaf(q4.z, Sreg[4*j + 2].y, o.y);
            o.x = fmaf(q4.w, Sreg[4*j + 3].x, o.x); o.y = fmaf(q4.w, Sreg[4*j + 3].y, o.y);
        }
        *reinterpret_cast<float2*>(y + (size_t)(t0 + tok) * DH + 2 * lane) = o;
    }
}

// ============================================================
extern "C" void kernel_launch(void* const* d_in, const int* in_sizes, int n_in,
                              void* d_out, int out_size) {
    (void)in_sizes; (void)n_in; (void)out_size;
    const float* x  = (const float*)d_in[0];
    const float* w  = (const float*)d_in[1];
    const float* Wq = (const float*)d_in[2];
    const float* bq = (const float*)d_in[3];
    const float* Wk = (const float*)d_in[4];
    const float* bk = (const float*)d_in[5];
    const float* Wv = (const float*)d_in[6];
    const float* bv = (const float*)d_in[7];
    float* y = (float*)d_out;

    static int attr_set = 0;
    if (!attr_set) {
        cudaFuncSetAttribute(phase1_kernel, cudaFuncAttributeMaxDynamicSharedMemorySize, DYN_BYTES);
        attr_set = 1;
    }

    prep_kernel<<<(EMB * NJ + 255) / 256, 256>>>(w, Wq, bq, Wk, bk, Wv, bv);
    phase1_kernel<<<NTILE, 256, DYN_BYTES>>>(x);
    reduce_kernel<<<(BATCH * NFEAT * DH) / 256, 256>>>();
    phase2_kernel<<<(BATCH * TLEN) / 128, 256>>>(y);
}

// round 11
// speedup vs baseline: 3.3440x; 1.0099x over previous
#include <cuda_runtime.h>
#include <cuda_fp16.h>
#include <math.h>
#include <stdint.h>

// Problem constants
#define BATCH 4
#define TLEN  8192
#define EMB   1024
#define DH    64
#define MF    8
#define NJ    80          // 8 p_q + 8 p_k + 64 v
#define TM    128         // tokens per phase-1 tile (MMA M)
#define KC    32          // K per staged chunk
#define NCHUNK (EMB/KC)   // 32
#define NTILE ((BATCH*TLEN)/TM)   // 256
#define NFEAT (2*MF)
#define INV_SQRT_M 0.35355339059327376f

// ---- device scratch (no allocations allowed) ----
__device__ __half g_WBh[EMB*NJ];          // folded W [e][j] fp16 hi (all 80 cols)
__device__ __half g_WBl[EMB*NJ];          // fp16 lo residual (used for cols 0..15)
__device__ float g_bias[NJ];
__device__ float g_qP[BATCH*TLEN*NFEAT];  // finished q features (2 MB)
__device__ float g_Spart[NTILE*NFEAT*DH];
__device__ float g_S[BATCH*NFEAT*DH];

// ---- smem stage layout ----
#define OFF_ALO 10240      // a_hi[128][40] fp16 = 10240 B
#define OFF_BHI 20480      // a_lo same size
#define OFF_BLO 26112      // b_hi[32][88] fp16 = 5632 B
#define STAGE_BYTES 27648  // b_lo[32][24] fp16 = 1536 B
#define DYN_BYTES (2 * STAGE_BYTES)   // 55296; res[128][82] (41984) aliases offset 0

// ---- helpers ----
__device__ __forceinline__ uint32_t smem_u32(const void* p) {
    uint32_t a;
    asm("{ .reg .u64 t; cvta.to.shared.u64 t, %1; cvt.u32.u64 %0, t; }" : "=r"(a) : "l"(p));
    return a;
}
__device__ __forceinline__ void ldsm_x4(uint32_t* r, uint32_t addr) {
    asm volatile("ldmatrix.sync.aligned.m8n8.x4.shared.b16 {%0,%1,%2,%3}, [%4];"
        : "=r"(r[0]), "=r"(r[1]), "=r"(r[2]), "=r"(r[3]) : "r"(addr));
}
__device__ __forceinline__ void ldsm_x4_t(uint32_t* r, uint32_t addr) {
    asm volatile("ldmatrix.sync.aligned.m8n8.x4.trans.shared.b16 {%0,%1,%2,%3}, [%4];"
        : "=r"(r[0]), "=r"(r[1]), "=r"(r[2]), "=r"(r[3]) : "r"(addr));
}
__device__ __forceinline__ void mma_f16(float* c, const uint32_t* a, const uint32_t* b) {
    asm volatile("mma.sync.aligned.m16n8k16.row.col.f32.f16.f16.f32 "
        "{%0,%1,%2,%3}, {%4,%5,%6,%7}, {%8,%9}, {%0,%1,%2,%3};"
        : "+f"(c[0]), "+f"(c[1]), "+f"(c[2]), "+f"(c[3])
        : "r"(a[0]), "r"(a[1]), "r"(a[2]), "r"(a[3]), "r"(b[0]), "r"(b[1]));
}
// split fp32 pair -> packed fp16 hi + fp16 lo(residual)
__device__ __forceinline__ void split_pack(float vx, float vy, uint32_t& hi, uint32_t& lo) {
    __half2 h = __floats2half2_rn(vx, vy);
    float2 hf = __half22float2(h);
    __half2 l = __floats2half2_rn(vx - hf.x, vy - hf.y);
    hi = *reinterpret_cast<uint32_t*>(&h);
    lo = *reinterpret_cast<uint32_t*>(&l);
}

// ============================================================
// prep: fold Wq@w, Wk@w + Wv into fp16 hi/lo [e][j]; biases.
// ============================================================
__global__ void prep_kernel(const float* __restrict__ w,
                            const float* __restrict__ Wq, const float* __restrict__ bq,
                            const float* __restrict__ Wk, const float* __restrict__ bk,
                            const float* __restrict__ Wv, const float* __restrict__ bv) {
    int g = blockIdx.x * blockDim.x + threadIdx.x;
    if (g < NJ) {
        float bb;
        if (g < MF) {
            bb = 0.f;
            for (int d = 0; d < DH; d++) bb += bq[d] * w[d*MF + g];
        } else if (g < 2*MF) {
            int jj = g - MF;
            bb = 0.f;
            for (int d = 0; d < DH; d++) bb += bk[d] * w[d*MF + jj];
        } else {
            bb = bv[g - 2*MF];
        }
        g_bias[g] = bb;
    }
    if (g >= EMB*NJ) return;
    int e = g / NJ;
    int j = g - e*NJ;
    float val;
    if (j < MF) {
        val = 0.f;
        for (int d = 0; d < DH; d++) val += Wq[e*DH + d] * w[d*MF + j];
    } else if (j < 2*MF) {
        int jj = j - MF;
        val = 0.f;
        for (int d = 0; d < DH; d++) val += Wk[e*DH + d] * w[d*MF + jj];
    } else {
        val = Wv[e*DH + (j - 2*MF)];
    }
    __half h = __float2half_rn(val);
    g_WBh[g] = h;
    g_WBl[g] = __float2half_rn(val - __half2float(h));
}

// ============================================================
// phase 1: pipelined HMMA fp16 GEMM [128 x 80]
//   p-cols (0..15): 3-term split; v-cols (16..79): 1-term hi*hi
// ============================================================
__global__ __launch_bounds__(256, 2) void phase1_kernel(const float* __restrict__ x) {
    extern __shared__ char smc[];
    const int tid  = threadIdx.x;
    const int lane = tid & 31;
    const int w    = tid >> 5;                 // warp 0..7 -> M rows 16w..16w+15
    const int tile = blockIdx.x;
    const float* xrow = x + (size_t)tile * TM * EMB;
    const uint32_t sbase = smem_u32(smc);

    // per-lane ldmatrix offsets (within a stage)
    const uint32_t aOffHi = (uint32_t)((16*w + (lane & 15)) * 80 + ((lane >> 4) * 8) * 2);
    const uint32_t bOffHi = (uint32_t)(OFF_BHI + (lane & 15) * 176 + ((lane >> 4) * 8) * 2);
    const uint32_t bOffLo = (uint32_t)(OFF_BLO + (lane & 15) * 48  + ((lane >> 4) * 8) * 2);

    // staging index precompute
    const int sa_tok = tid >> 3;               // A: token (i term adds 32)
    const int sa_k4  = (tid & 7) << 2;
    const int sl_k   = tid >> 3;               // B lo: k row 0..31
    const int sl_jp  = tid & 7;                // u32 col 0..7 (fp16 cols 0..15)

    float acc[10][4];
    #pragma unroll
    for (int nt = 0; nt < 10; nt++)
        #pragma unroll
        for (int i = 0; i < 4; i++) acc[nt][i] = 0.f;

    // ---- prologue: stage chunk 0 into stage 0 ----
    {
        char* sb = smc;
        #pragma unroll
        for (int i = 0; i < 4; i++) {
            int tok = sa_tok + i * 32;
            float4 v = *reinterpret_cast<const float4*>(xrow + (size_t)tok * EMB + sa_k4);
            uint32_t h0, l0, h1, l1;
            split_pack(v.x, v.y, h0, l0);
            split_pack(v.z, v.w, h1, l1);
            uint32_t off = (uint32_t)(tok * 80 + sa_k4 * 2);
            *reinterpret_cast<uint2*>(sb + off)           = make_uint2(h0, h1);
            *reinterpret_cast<uint2*>(sb + OFF_ALO + off) = make_uint2(l0, l1);
        }
        #pragma unroll
        for (int i = 0; i < 5; i++) {
            int idx = tid + i * 256;
            int k  = idx / 40;
            int jp = idx - k * 40;
            *reinterpret_cast<uint32_t*>(sb + OFF_BHI + k * 176 + jp * 4) =
                *reinterpret_cast<const uint32_t*>(&g_WBh[(size_t)k * NJ + 2 * jp]);
        }
        *reinterpret_cast<uint32_t*>(sb + OFF_BLO + sl_k * 48 + sl_jp * 4) =
            *reinterpret_cast<const uint32_t*>(&g_WBl[(size_t)sl_k * NJ + 2 * sl_jp]);
    }
    __syncthreads();

    // ---- pipelined main loop ----
    for (int c = 0; c < NCHUNK; c++) {
        const uint32_t sOff = (uint32_t)((c & 1) * STAGE_BYTES);
        const int nxt = c + 1;

        // 1) prefetch chunk c+1 into registers
        float4 va[4];
        uint32_t wh[5], wl0;
        if (nxt < NCHUNK) {
            const int ko = nxt * KC;
            #pragma unroll
            for (int i = 0; i < 4; i++) {
                int tok = sa_tok + i * 32;
                va[i] = *reinterpret_cast<const float4*>(xrow + (size_t)tok * EMB + ko + sa_k4);
            }
            #pragma unroll
            for (int i = 0; i < 5; i++) {
                int idx = tid + i * 256;
                int k  = idx / 40;
                int jp = idx - k * 40;
                wh[i] = *reinterpret_cast<const uint32_t*>(&g_WBh[(size_t)(ko + k) * NJ + 2 * jp]);
            }
            wl0 = *reinterpret_cast<const uint32_t*>(&g_WBl[(size_t)(ko + sl_k) * NJ + 2 * sl_jp]);
        }

        // 2) compute chunk c from stage (c&1)
        const uint32_t aHiAddr = sbase + sOff + aOffHi;
        const uint32_t aLoAddr = aHiAddr + OFF_ALO;
        const uint32_t bHiAddr = sbase + sOff + bOffHi;
        const uint32_t bLoAddr = sbase + sOff + bOffLo;
        #pragma unroll
        for (int ks = 0; ks < 2; ks++) {
            uint32_t Ah[4], Al[4];
            ldsm_x4(Ah, aHiAddr + ks * 32);
            ldsm_x4(Al, aLoAddr + ks * 32);
            // np = 0 : p-columns 0..15, 3-term split
            {
                uint32_t Bh[4], Bl[4];
                ldsm_x4_t(Bh, bHiAddr + ks * 2816);
                ldsm_x4_t(Bl, bLoAddr + ks * 768);
                mma_f16(acc[0], Ah, Bh + 0);
                mma_f16(acc[1], Ah, Bh + 2);
                mma_f16(acc[0], Ah, Bl + 0);
                mma_f16(acc[1], Ah, Bl + 2);
                mma_f16(acc[0], Al, Bh + 0);
                mma_f16(acc[1], Al, Bh + 2);
            }
            // np = 1..4 : v-columns, 1-term hi*hi
            #pragma unroll
            for (int np = 1; np < 5; np++) {
                uint32_t Bh[4];
                ldsm_x4_t(Bh, bHiAddr + ks * 2816 + np * 32);
                mma_f16(acc[2*np],     Ah, Bh + 0);
                mma_f16(acc[2*np + 1], Ah, Bh + 2);
            }
        }

        // 3) convert + store chunk c+1 into stage ((c+1)&1)
        if (nxt < NCHUNK) {
            char* sb = smc + (nxt & 1) * STAGE_BYTES;
            #pragma unroll
            for (int i = 0; i < 4; i++) {
                int tok = sa_tok + i * 32;
                uint32_t h0, l0, h1, l1;
                split_pack(va[i].x, va[i].y, h0, l0);
                split_pack(va[i].z, va[i].w, h1, l1);
                uint32_t off = (uint32_t)(tok * 80 + sa_k4 * 2);
                *reinterpret_cast<uint2*>(sb + off)           = make_uint2(h0, h1);
                *reinterpret_cast<uint2*>(sb + OFF_ALO + off) = make_uint2(l0, l1);
            }
            #pragma unroll
            for (int i = 0; i < 5; i++) {
                int idx = tid + i * 256;
                int k  = idx / 40;
                int jp = idx - k * 40;
                *reinterpret_cast<uint32_t*>(sb + OFF_BHI + k * 176 + jp * 4) = wh[i];
            }
            *reinterpret_cast<uint32_t*>(sb + OFF_BLO + sl_k * 48 + sl_jp * 4) = wl0;
        }
        __syncthreads();
    }

    // ---- epilogue: C frags + bias -> res[tok][82] (aliases stage smem) ----
    float (*res)[82] = reinterpret_cast<float (*)[82]>(smc);
    {
        int r0 = 16 * w + (lane >> 2);
        #pragma unroll
        for (int nt = 0; nt < 10; nt++) {
            int col = nt * 8 + 2 * (lane & 3);
            float b0 = g_bias[col], b1 = g_bias[col + 1];
            *reinterpret_cast<float2*>(&res[r0][col]) =
                make_float2(acc[nt][0] + b0, acc[nt][1] + b1);
            *reinterpret_cast<float2*>(&res[r0 + 8][col]) =
                make_float2(acc[nt][2] + b0, acc[nt][3] + b1);
        }
    }
    __syncthreads();

    const int t0 = tile * TM;
    // q-path: sincos here, store finished qP (cos 0..7 | sin 8..15)
    #pragma unroll
    for (int i = 0; i < 4; i++) {
        int idx = tid + i * 256;                // tok*8 + m
        int tok = idx >> 3;
        int mq  = idx & 7;
        float p = res[tok][mq];
        float sv, cv;
        sincosf(p, &sv, &cv);
        float* qp = g_qP + (size_t)(t0 + tok) * NFEAT;
        qp[mq]      = cv * INV_SQRT_M;
        qp[MF + mq] = sv * INV_SQRT_M;
    }
    __syncthreads();
    // k-path: Kp in place: cos -> 0..7, sin -> 8..15
    #pragma unroll
    for (int i = 0; i < 4; i++) {
        int idx = tid + i * 256;
        int tok = idx >> 3;
        int mm  = idx & 7;
        float p = res[tok][MF + mm];
        float sv, cv;
        sincosf(p, &sv, &cv);
        res[tok][mm]      = cv * INV_SQRT_M;
        res[tok][MF + mm] = sv * INV_SQRT_M;
    }
    __syncthreads();
    // partial S[16][64] for this tile (deterministic per-tile slab)
    const int d  = tid & 63;
    const int fg = tid >> 6;
    float sacc[4] = {0.f, 0.f, 0.f, 0.f};
    for (int tok = 0; tok < TM; tok++) {
        const float* rr = res[tok];
        float v = rr[2 * MF + d];
        #pragma unroll
        for (int ff = 0; ff < 4; ff++)
            sacc[ff] = fmaf(rr[fg * 4 + ff], v, sacc[ff]);
    }
    float* Sp = g_Spart + (size_t)tile * (NFEAT * DH);
    #pragma unroll
    for (int ff = 0; ff < 4; ff++)
        Sp[(fg * 4 + ff) * DH + d] = sacc[ff];
}

// ============================================================
// reduce: S[b][f][d] = sum over 64 tiles (deterministic order)
// ============================================================
__global__ void reduce_kernel() {
    int g  = blockIdx.x * blockDim.x + threadIdx.x;   // 0..4095
    int b  = g >> 10;
    int fd = g & 1023;
    const float* bs = g_Spart + (size_t)b * 64 * (NFEAT * DH) + fd;
    float s = 0.f;
    #pragma unroll
    for (int tt = 0; tt < 64; tt++) s += bs[(size_t)tt * (NFEAT * DH)];
    g_S[g] = s;
}

// ============================================================
// phase 2: y[t][d] = sum_f qP[t][f] * S[b][f][d]
// lane owns a d-pair (S column pair in regs); warp does 16 tokens
// ============================================================
__global__ __launch_bounds__(256) void phase2_kernel(float* __restrict__ y) {
    __shared__ float Ss[NFEAT * DH];    // 4 KB
    __shared__ float qs[128][20];       // 10 KB (pad 20 keeps float4 stores aligned)
    const int tid  = threadIdx.x;
    const int lane = tid & 31;
    const int wp   = tid >> 5;
    const int t0   = blockIdx.x * 128;  // 128 tokens per block (no batch straddle)
    const int b    = t0 / TLEN;

    #pragma unroll
    for (int i = 0; i < 4; i++) Ss[tid + i * 256] = g_S[b * (NFEAT * DH) + tid + i * 256];
    #pragma unroll
    for (int i = 0; i < 2; i++) {
        int idx = tid + i * 256;        // 0..511 float4s: tok = idx>>2, grp = idx&3
        float4 v = *reinterpret_cast<const float4*>(g_qP + (size_t)t0 * NFEAT + idx * 4);
        *reinterpret_cast<float4*>(&qs[idx >> 2][(idx & 3) * 4]) = v;
    }
    __syncthreads();

    // preload this lane's S column pair (d = 2*lane, 2*lane+1)
    float2 Sreg[NFEAT];
    #pragma unroll
    for (int f = 0; f < NFEAT; f++)
        Sreg[f] = *reinterpret_cast<const float2*>(&Ss[f * DH + 2 * lane]);

    #pragma unroll 4
    for (int it = 0; it < 16; it++) {
        int tok = wp * 16 + it;
        const float4* qv = reinterpret_cast<const float4*>(qs[tok]);   // broadcast reads
        float2 o = make_float2(0.f, 0.f);
        #pragma unroll
        for (int j = 0; j < 4; j++) {
            float4 q4 = qv[j];
            o.x = fmaf(q4.x, Sreg[4*j + 0].x, o.x); o.y = fmaf(q4.x, Sreg[4*j + 0].y, o.y);
            o.x = fmaf(q4.y, Sreg[4*j + 1].x, o.x); o.y = fmaf(q4.y, Sreg[4*j + 1].y, o.y);
            o.x = fmaf(q4.z, Sreg[4*j + 2].x, o.x); o.y = fmaf(q4.z, Sreg[4*j + 2].y, o.y);
            o.x = fmaf(q4.w, Sreg[4*j + 3].x, o.x); o.y = fmaf(q4.w, Sreg[4*j + 3].y, o.y);
        }
        *reinterpret_cast<float2*>(y + (size_t)(t0 + tok) * DH + 2 * lane) = o;
    }
}

// ============================================================
extern "C" void kernel_launch(void* const* d_in, const int* in_sizes, int n_in,
                              void* d_out, int out_size) {
    (void)in_sizes; (void)n_in; (void)out_size;
    const float* x  = (const float*)d_in[0];
    const float* w  = (const float*)d_in[1];
    const float* Wq = (const float*)d_in[2];
    const float* bq = (const float*)d_in[3];
    const float* Wk = (const float*)d_in[4];
    const float* bk = (const float*)d_in[5];
    const float* Wv = (const float*)d_in[6];
    const float* bv = (const float*)d_in[7];
    float* y = (float*)d_out;

    static int attr_set = 0;
    if (!attr_set) {
        cudaFuncSetAttribute(phase1_kernel, cudaFuncAttributeMaxDynamicSharedMemorySize, DYN_BYTES);
        attr_set = 1;
    }

    prep_kernel<<<(EMB * NJ + 255) / 256, 256>>>(w, Wq, bq, Wk, bk, Wv, bv);
    phase1_kernel<<<NTILE, 256, DYN_BYTES>>>(x);
    reduce_kernel<<<(BATCH * NFEAT * DH) / 256, 256>>>();
    phase2_kernel<<<(BATCH * TLEN) / 128, 256>>>(y);
}